// round 1
// baseline (speedup 1.0000x reference)
#include <cuda_runtime.h>
#include <math.h>

#define C_CLASSES 21
#define CC 441            // C*C
#define EPS 1e-10f

// Per-batch constants computed by setup kernel.
__device__ float g_dv[256];    // diag of q_small
__device__ float g_ov[256];    // off-diag of q_small
__device__ float g_Lo[256];    // log(off + eps)
__device__ float g_dLd[256];   // log(diag + eps) - log(off + eps)

// ---------------------------------------------------------------------------
// Kernel 1: per-batch alpha_cumprod walk (200 steps max, 64 threads total).
// Internally double; matches jnp f32 pipeline to well within 1e-3.
// ---------------------------------------------------------------------------
__global__ void setup_kernel(const int* __restrict__ t, int B) {
    int b = blockIdx.x * blockDim.x + threadIdx.x;
    if (b >= B) return;
    int tb = t[b];

    const double inv   = 1.0 / (1.0 + 1e-4);
    const double halfpi = 1.5707963267948966;
    double c0 = cos(1e-4 * inv * halfpi);
    double prev = c0 * c0;                    // ac[0] (normalization cancels in ratios)
    double prod = 1.0;
    for (int i = 0; i <= tb; ++i) {
        double s  = (double)(i + 1) / 200.0;
        double c  = cos((s + 1e-4) * inv * halfpi);
        double ac = c * c;
        double beta = 1.0 - ac / prev;
        beta = fmin(fmax(beta, 0.0), 0.999);  // jnp.clip(..., 0, 0.999)
        prod *= (1.0 - beta);
        prev = ac;
    }
    float alpha = (float)prod;
    float off   = (1.0f - alpha) * (float)(1.0 / 21.0);
    float diag  = alpha + off;
    float Lo    = logf(off + EPS);
    float Ld    = logf(diag + EPS);
    g_dv[b]  = diag;
    g_ov[b]  = off;
    g_Lo[b]  = Lo;
    g_dLd[b] = Ld - Lo;
}

// ---------------------------------------------------------------------------
// Kernel 2: logits[b,s,d] = Lo*rowsum + (Ld-Lo)*x[b,s,d]
// 256 rows per block (requires S % 256 == 0 so each block is single-batch).
// ---------------------------------------------------------------------------
__global__ __launch_bounds__(256) void logits_kernel(
    const float* __restrict__ x, float* __restrict__ out, int S) {
    __shared__ float tile[256 * C_CLASSES];
    __shared__ float rs[256];
    const int tid = threadIdx.x;
    const size_t base = (size_t)blockIdx.x * (256 * C_CLASSES);

    const float* xin = x + base;
    #pragma unroll
    for (int k = 0; k < C_CLASSES; ++k) {
        int i = tid + k * 256;
        tile[i] = xin[i];
    }
    __syncthreads();

    float s = 0.0f;
    const int r0 = tid * C_CLASSES;
    #pragma unroll
    for (int j = 0; j < C_CLASSES; ++j) s += tile[r0 + j];
    rs[tid] = s;
    __syncthreads();

    const int b = (int)(((long long)blockIdx.x * 256) / S);
    const float Lo  = g_Lo[b];
    const float dLd = g_dLd[b];
    float* o = out + base;
    #pragma unroll
    for (int k = 0; k < C_CLASSES; ++k) {
        int i = tid + k * 256;
        int row = (int)(((unsigned)i * 6242u) >> 17);   // i / 21 for i < 5376 (verified)
        o[i] = fmaf(dLd, tile[i], Lo * rs[row]);
    }
}

// ---------------------------------------------------------------------------
// Kernel 3 (hot path): fill q_t = broadcast of q_small over S. 462 MB stores.
// blockDim = 441 threads (one per float4-column residue of the CC=441 period).
// Grid stride between iterations is a multiple of 441 floats, so each thread's
// float4 payload is loop-invariant: compute once, then ITERS bare STG.128.
// Per batch: grid.x blocks * 441 threads * ITERS float4 = S*441/4 float4.
// ---------------------------------------------------------------------------
template <int ITERS>
__global__ __launch_bounds__(448) void qt_kernel(
    float4* __restrict__ out, int f4_per_batch, int stride_f4) {
    const int b   = blockIdx.y;
    const int tid = threadIdx.x;           // 0..440
    const float dv = g_dv[b];
    const float ov = g_ov[b];

    // period position of this thread's 4 elements: p = (4*tid + k) mod 441
    int p0 = 4 * tid;
    if (p0 >= CC) p0 -= CC;                 // 4*tid < 1764 = 4*441
    if (p0 >= CC) p0 -= CC;
    if (p0 >= CC) p0 -= CC;
    float v[4];
    #pragma unroll
    for (int k = 0; k < 4; ++k) {
        int p = p0 + k;
        if (p >= CC) p -= CC;
        v[k] = (p % 22 == 0) ? dv : ov;     // diag positions: p = 22*c
    }
    const float4 val = make_float4(v[0], v[1], v[2], v[3]);

    float4* o = out + (size_t)b * f4_per_batch
                    + (size_t)blockIdx.x * CC + tid;
    #pragma unroll
    for (int it = 0; it < ITERS; ++it)
        o[(size_t)it * stride_f4] = val;
}

// Generic scalar fallback for unexpected shapes.
__global__ void qt_generic_kernel(float* __restrict__ out, long long n,
                                  long long per_batch) {
    long long stride = (long long)gridDim.x * blockDim.x;
    for (long long i = (long long)blockIdx.x * blockDim.x + threadIdx.x;
         i < n; i += stride) {
        int b = (int)(i / per_batch);
        int p = (int)((i % per_batch) % CC);
        out[i] = (p % 22 == 0) ? g_dv[b] : g_ov[b];
    }
}

extern "C" void kernel_launch(void* const* d_in, const int* in_sizes, int n_in,
                              void* d_out, int out_size) {
    const float* x = (const float*)d_in[0];
    const int*   t = (const int*)d_in[1];
    const int C = C_CLASSES;
    const int B = in_sizes[1];
    const int total = in_sizes[0];          // B*S*C
    const int S = total / (B * C);

    setup_kernel<<<1, (B + 31) & ~31>>>(t, B);

    // logits
    long long rows = (long long)B * S;
    if (S % 256 == 0) {
        int nblocks = (int)(rows / 256);
        logits_kernel<<<nblocks, 256>>>(x, (float*)d_out, S);
    }

    // q_t (only if harness expects both outputs concatenated)
    long long logits_elems = (long long)B * S * C;
    long long qt_elems = (long long)B * S * C * C;
    if ((long long)out_size >= logits_elems + qt_elems) {
        float* qt = (float*)d_out + logits_elems;
        if (S % 64 == 0) {
            const int ITERS = 16;
            int blocks_x = S / (4 * ITERS);          // S/64: per-batch f4 = blocks_x*441*ITERS
            int f4_per_batch = (S * CC) / 4;
            int stride_f4 = blocks_x * CC;
            dim3 grid(blocks_x, B);
            qt_kernel<ITERS><<<grid, CC>>>((float4*)qt, f4_per_batch, stride_f4);
        } else {
            qt_generic_kernel<<<2048, 256>>>(qt, qt_elems, (long long)S * CC);
        }
    }
}

// round 2
// speedup vs baseline: 4.5049x; 4.5049x over previous
#include <cuda_runtime.h>
#include <math.h>

#define C_CLASSES 21
#define CC 441            // C*C
#define EPS 1e-10f
#define T_STEPS 200

// Per-batch constants computed by setup kernel.
__device__ float g_dv[256];    // diag of q_small
__device__ float g_ov[256];    // off-diag of q_small
__device__ float g_Lo[256];    // log(off + eps)
__device__ float g_dLd[256];   // log(diag + eps) - log(off + eps)

// ---------------------------------------------------------------------------
// Kernel 1: alpha_cumprod table computed ONCE, in parallel.
//   threads 0..200: ac[i] = cos^2((i/200 + 1e-4)/(1+1e-4) * pi/2)  (1 cos each)
//   threads 0..199: alphas[i] = 1 - clip(1 - ac[i+1]/ac[i], 0, 0.999)
//   thread 0:       serial float cumprod (200 FMULs, negligible)
//   threads b<B:    gather alpha_cum[t[b]], write per-batch constants
// Single block, 256 threads. Dependency depth ~ one double cos + 800 cyc.
// ---------------------------------------------------------------------------
__global__ __launch_bounds__(256) void setup_kernel(const int* __restrict__ t, int B) {
    __shared__ double ac[T_STEPS + 1];
    __shared__ float alphas[T_STEPS];
    __shared__ float acum[T_STEPS];
    const int tid = threadIdx.x;

    if (tid <= T_STEPS) {
        const double inv    = 1.0 / (1.0 + 1e-4);
        const double halfpi = 1.5707963267948966;
        double s = (double)tid / (double)T_STEPS;
        double c = cos((s + 1e-4) * inv * halfpi);
        ac[tid] = c * c;            // normalization by ac[0] cancels in ratios
    }
    __syncthreads();

    if (tid < T_STEPS) {
        double beta = 1.0 - ac[tid + 1] / ac[tid];
        beta = fmin(fmax(beta, 0.0), 0.999);
        alphas[tid] = (float)(1.0 - beta);
    }
    __syncthreads();

    if (tid == 0) {
        float p = 1.0f;
        #pragma unroll 8
        for (int i = 0; i < T_STEPS; ++i) {
            p *= alphas[i];
            acum[i] = p;
        }
    }
    __syncthreads();

    if (tid < B) {
        float alpha = acum[t[tid]];
        float off   = (1.0f - alpha) * (float)(1.0 / 21.0);
        float diag  = alpha + off;
        float Lo    = logf(off + EPS);
        float Ld    = logf(diag + EPS);
        g_dv[tid]  = diag;
        g_ov[tid]  = off;
        g_Lo[tid]  = Lo;
        g_dLd[tid] = Ld - Lo;
    }
}

// ---------------------------------------------------------------------------
// Kernel 2: logits[b,s,d] = Lo*rowsum + (Ld-Lo)*x[b,s,d]
// 256 rows per block (requires S % 256 == 0 so each block is single-batch).
// ---------------------------------------------------------------------------
__global__ __launch_bounds__(256) void logits_kernel(
    const float* __restrict__ x, float* __restrict__ out, int S) {
    __shared__ float tile[256 * C_CLASSES];
    __shared__ float rs[256];
    const int tid = threadIdx.x;
    const size_t base = (size_t)blockIdx.x * (256 * C_CLASSES);

    const float* xin = x + base;
    #pragma unroll
    for (int k = 0; k < C_CLASSES; ++k) {
        int i = tid + k * 256;
        tile[i] = xin[i];
    }
    __syncthreads();

    float s = 0.0f;
    const int r0 = tid * C_CLASSES;
    #pragma unroll
    for (int j = 0; j < C_CLASSES; ++j) s += tile[r0 + j];
    rs[tid] = s;
    __syncthreads();

    const int b = (int)(((long long)blockIdx.x * 256) / S);
    const float Lo  = g_Lo[b];
    const float dLd = g_dLd[b];
    float* o = out + base;
    #pragma unroll
    for (int k = 0; k < C_CLASSES; ++k) {
        int i = tid + k * 256;
        int row = (int)(((unsigned)i * 6242u) >> 17);   // i / 21 for i < 5376 (verified)
        o[i] = fmaf(dLd, tile[i], Lo * rs[row]);
    }
}

// ---------------------------------------------------------------------------
// Kernel 3 (hot path): fill q_t = broadcast of q_small over S. 462 MB stores.
// blockDim = 441 threads (one per float4-column residue of the CC=441 period).
// Grid stride between iterations is a multiple of 441 floats, so each thread's
// float4 payload is loop-invariant: compute once, then ITERS bare STG.128.
// ---------------------------------------------------------------------------
template <int ITERS>
__global__ __launch_bounds__(448) void qt_kernel(
    float4* __restrict__ out, int f4_per_batch, int stride_f4) {
    const int b   = blockIdx.y;
    const int tid = threadIdx.x;           // 0..440
    const float dv = g_dv[b];
    const float ov = g_ov[b];

    // period position of this thread's 4 elements: p = (4*tid + k) mod 441
    int p0 = 4 * tid;
    if (p0 >= CC) p0 -= CC;                 // 4*tid < 1764 = 4*441
    if (p0 >= CC) p0 -= CC;
    if (p0 >= CC) p0 -= CC;
    float v[4];
    #pragma unroll
    for (int k = 0; k < 4; ++k) {
        int p = p0 + k;
        if (p >= CC) p -= CC;
        v[k] = (p % 22 == 0) ? dv : ov;     // diag positions: p = 22*c
    }
    const float4 val = make_float4(v[0], v[1], v[2], v[3]);

    float4* o = out + (size_t)b * f4_per_batch
                    + (size_t)blockIdx.x * CC + tid;
    #pragma unroll
    for (int it = 0; it < ITERS; ++it)
        o[(size_t)it * stride_f4] = val;
}

// Generic scalar fallback for unexpected shapes.
__global__ void qt_generic_kernel(float* __restrict__ out, long long n,
                                  long long per_batch) {
    long long stride = (long long)gridDim.x * blockDim.x;
    for (long long i = (long long)blockIdx.x * blockDim.x + threadIdx.x;
         i < n; i += stride) {
        int b = (int)(i / per_batch);
        int p = (int)((i % per_batch) % CC);
        out[i] = (p % 22 == 0) ? g_dv[b] : g_ov[b];
    }
}

extern "C" void kernel_launch(void* const* d_in, const int* in_sizes, int n_in,
                              void* d_out, int out_size) {
    const float* x = (const float*)d_in[0];
    const int*   t = (const int*)d_in[1];
    const int C = C_CLASSES;
    const int B = in_sizes[1];
    const int total = in_sizes[0];          // B*S*C
    const int S = total / (B * C);

    setup_kernel<<<1, 256>>>(t, B);

    // logits
    long long rows = (long long)B * S;
    if (S % 256 == 0) {
        int nblocks = (int)(rows / 256);
        logits_kernel<<<nblocks, 256>>>(x, (float*)d_out, S);
    }

    // q_t (only if harness expects both outputs concatenated)
    long long logits_elems = (long long)B * S * C;
    long long qt_elems = (long long)B * S * C * C;
    if ((long long)out_size >= logits_elems + qt_elems) {
        float* qt = (float*)d_out + logits_elems;
        if (S % 64 == 0) {
            const int ITERS = 16;
            int blocks_x = S / (4 * ITERS);          // S/64: per-batch f4 = blocks_x*441*ITERS
            int f4_per_batch = (S * CC) / 4;
            int stride_f4 = blocks_x * CC;
            dim3 grid(blocks_x, B);
            qt_kernel<ITERS><<<grid, CC>>>((float4*)qt, f4_per_batch, stride_f4);
        } else {
            qt_generic_kernel<<<2048, 256>>>(qt, qt_elems, (long long)S * CC);
        }
    }
}

// round 3
// speedup vs baseline: 4.8472x; 1.0760x over previous
#include <cuda_runtime.h>
#include <math.h>

#define C_CLASSES 21
#define CC 441            // C*C
#define EPS 1e-10f
#define T_STEPS 200

// Per-batch constants computed by setup kernel.
__device__ float g_dv[256];    // diag of q_small
__device__ float g_ov[256];    // off-diag of q_small
__device__ float g_Lo[256];    // log(off + eps)
__device__ float g_dLd[256];   // log(diag + eps) - log(off + eps)

// ---------------------------------------------------------------------------
// Kernel 1: alpha_cumprod table computed ONCE, all-fp32 (matches jnp f32),
// with a parallel Hillis-Steele product scan instead of a serial cumprod.
//   threads 0..200: ac[i] = cos^2((i/200 + 1e-4)/(1+1e-4) * pi/2)   (1 cosf)
//   threads 0..199: a[i]  = 1 - clip(1 - ac[i+1]/ac[i], 0, 0.999)
//   scan:           acum[i] = prod_{j<=i} a[j]   (8 steps, double-buffered)
//   threads b<B:    gather acum[t[b]], write per-batch constants
// ---------------------------------------------------------------------------
__global__ __launch_bounds__(256) void setup_kernel(const int* __restrict__ t, int B) {
    __shared__ float ac[T_STEPS + 1];
    __shared__ float buf0[256];
    __shared__ float buf1[256];
    const int tid = threadIdx.x;

    if (tid <= T_STEPS) {
        const float inv    = 1.0f / (1.0f + 1e-4f);
        const float halfpi = 1.57079632679489662f;
        float s = (float)tid * (1.0f / (float)T_STEPS);
        float c = cosf((s + 1e-4f) * inv * halfpi);
        ac[tid] = c * c;            // normalization by ac[0] cancels in ratios
    }
    __syncthreads();

    float v = 1.0f;
    if (tid < T_STEPS) {
        float beta = 1.0f - ac[tid + 1] / ac[tid];
        beta = fminf(fmaxf(beta, 0.0f), 0.999f);
        v = 1.0f - beta;
    }
    buf0[tid] = v;
    __syncthreads();

    // Inclusive product scan over 256 lanes (only first 200 meaningful).
    float* src = buf0;
    float* dst = buf1;
    #pragma unroll
    for (int off = 1; off < 256; off <<= 1) {
        float w = src[tid];
        if (tid >= off) w *= src[tid - off];
        dst[tid] = w;
        __syncthreads();
        float* tmp = src; src = dst; dst = tmp;
    }
    // src now holds acum[i] = prod_{j<=i} alphas[j]

    if (tid < B) {
        float alpha = src[t[tid]];
        float off   = (1.0f - alpha) * (float)(1.0 / 21.0);
        float diag  = alpha + off;
        float Lo    = logf(off + EPS);
        float Ld    = logf(diag + EPS);
        g_dv[tid]  = diag;
        g_ov[tid]  = off;
        g_Lo[tid]  = Lo;
        g_dLd[tid] = Ld - Lo;
    }
}

// ---------------------------------------------------------------------------
// Kernel 2: logits[b,s,d] = Lo*rowsum + (Ld-Lo)*x[b,s,d]
// 256 rows per block (requires S % 256 == 0 so each block is single-batch).
// ---------------------------------------------------------------------------
__global__ __launch_bounds__(256) void logits_kernel(
    const float* __restrict__ x, float* __restrict__ out, int S) {
    __shared__ float tile[256 * C_CLASSES];
    __shared__ float rs[256];
    const int tid = threadIdx.x;
    const size_t base = (size_t)blockIdx.x * (256 * C_CLASSES);

    const float* xin = x + base;
    #pragma unroll
    for (int k = 0; k < C_CLASSES; ++k) {
        int i = tid + k * 256;
        tile[i] = xin[i];
    }
    __syncthreads();

    float s = 0.0f;
    const int r0 = tid * C_CLASSES;
    #pragma unroll
    for (int j = 0; j < C_CLASSES; ++j) s += tile[r0 + j];
    rs[tid] = s;
    __syncthreads();

    const int b = (int)(((long long)blockIdx.x * 256) / S);
    const float Lo  = g_Lo[b];
    const float dLd = g_dLd[b];
    float* o = out + base;
    #pragma unroll
    for (int k = 0; k < C_CLASSES; ++k) {
        int i = tid + k * 256;
        int row = (int)(((unsigned)i * 6242u) >> 17);   // i / 21 for i < 5376 (verified)
        o[i] = fmaf(dLd, tile[i], Lo * rs[row]);
    }
}

// ---------------------------------------------------------------------------
// Kernel 3 (hot path): fill q_t = broadcast of q_small over S. 462 MB stores.
// blockDim = 441 threads (one per float4-column residue of the CC=441 period).
// Grid stride between iterations is a multiple of 441 floats, so each thread's
// float4 payload is loop-invariant: compute once, then ITERS bare STG.128.
// ---------------------------------------------------------------------------
template <int ITERS>
__global__ __launch_bounds__(448) void qt_kernel(
    float4* __restrict__ out, int f4_per_batch, int stride_f4) {
    const int b   = blockIdx.y;
    const int tid = threadIdx.x;           // 0..440
    const float dv = g_dv[b];
    const float ov = g_ov[b];

    // period position of this thread's 4 elements: p = (4*tid + k) mod 441
    int p0 = 4 * tid;
    if (p0 >= CC) p0 -= CC;                 // 4*tid < 1764 = 4*441
    if (p0 >= CC) p0 -= CC;
    if (p0 >= CC) p0 -= CC;
    float v[4];
    #pragma unroll
    for (int k = 0; k < 4; ++k) {
        int p = p0 + k;
        if (p >= CC) p -= CC;
        v[k] = (p % 22 == 0) ? dv : ov;     // diag positions: p = 22*c
    }
    const float4 val = make_float4(v[0], v[1], v[2], v[3]);

    float4* o = out + (size_t)b * f4_per_batch
                    + (size_t)blockIdx.x * CC + tid;
    #pragma unroll
    for (int it = 0; it < ITERS; ++it)
        o[(size_t)it * stride_f4] = val;
}

// Generic scalar fallback for unexpected shapes.
__global__ void qt_generic_kernel(float* __restrict__ out, long long n,
                                  long long per_batch) {
    long long stride = (long long)gridDim.x * blockDim.x;
    for (long long i = (long long)blockIdx.x * blockDim.x + threadIdx.x;
         i < n; i += stride) {
        int b = (int)(i / per_batch);
        int p = (int)((i % per_batch) % CC);
        out[i] = (p % 22 == 0) ? g_dv[b] : g_ov[b];
    }
}

extern "C" void kernel_launch(void* const* d_in, const int* in_sizes, int n_in,
                              void* d_out, int out_size) {
    const float* x = (const float*)d_in[0];
    const int*   t = (const int*)d_in[1];
    const int C = C_CLASSES;
    const int B = in_sizes[1];
    const int total = in_sizes[0];          // B*S*C
    const int S = total / (B * C);

    setup_kernel<<<1, 256>>>(t, B);

    // logits
    long long rows = (long long)B * S;
    if (S % 256 == 0) {
        int nblocks = (int)(rows / 256);
        logits_kernel<<<nblocks, 256>>>(x, (float*)d_out, S);
    }

    // q_t (only if harness expects both outputs concatenated)
    long long logits_elems = (long long)B * S * C;
    long long qt_elems = (long long)B * S * C * C;
    if ((long long)out_size >= logits_elems + qt_elems) {
        float* qt = (float*)d_out + logits_elems;
        if (S % 64 == 0) {
            const int ITERS = 16;
            int blocks_x = S / (4 * ITERS);          // S/64: per-batch f4 = blocks_x*441*ITERS
            int f4_per_batch = (S * CC) / 4;
            int stride_f4 = blocks_x * CC;
            dim3 grid(blocks_x, B);
            qt_kernel<ITERS><<<grid, CC>>>((float4*)qt, f4_per_batch, stride_f4);
        } else {
            qt_generic_kernel<<<2048, 256>>>(qt, qt_elems, (long long)S * CC);
        }
    }
}